// round 12
// baseline (speedup 1.0000x reference)
#include <cuda_runtime.h>
#include <cuda_fp16.h>
#include <math.h>
#include <stdint.h>

#define HWX 256
#define CC 64
#define GG 48
#define NPAIR (48*48)
#define EPSV 1e-5

// ---------------- global scratch (no allocations allowed) ----------------
// Statically zeroed; the last CTA resets them after use so every graph replay
// sees zeros again (deterministic).
__device__ double g_sum_d = 0.0;
__device__ double g_sumsq_d = 0.0;
__device__ unsigned int g_count = 0;
__device__ float  g_dot[NPAIR];

__device__ __forceinline__ double warpRedD(double v) {
    #pragma unroll
    for (int o = 16; o > 0; o >>= 1)
        v += __shfl_xor_sync(0xffffffffu, v, o);
    return v;
}

__device__ __forceinline__ uint32_t smem_u32(const void* p) {
    uint32_t a;
    asm("{ .reg .u64 t; cvta.to.shared.u64 t, %1; cvt.u32.u64 %0, t; }" : "=r"(a) : "l"(p));
    return a;
}

// ldmatrix x4 transposed (b16) — baseline PTX, works on sm_103 (non-'a')
#define LDSM4T(r, addr) \
    asm volatile("ldmatrix.sync.aligned.m8n8.x4.trans.shared.b16 {%0,%1,%2,%3}, [%4];" \
        : "=r"((r)[0]), "=r"((r)[1]), "=r"((r)[2]), "=r"((r)[3]) : "r"(addr))

// mma.sync m16n8k16 fp16 -> f32 accum — baseline PTX
#define MMA16816(d, a, b0v, b1v) \
    asm volatile("mma.sync.aligned.m16n8k16.row.col.f32.f16.f16.f32 " \
        "{%0,%1,%2,%3}, {%4,%5,%6,%7}, {%8,%9}, {%0,%1,%2,%3};" \
        : "+f"((d)[0]), "+f"((d)[1]), "+f"((d)[2]), "+f"((d)[3]) \
        : "r"((a)[0]), "r"((a)[1]), "r"((a)[2]), "r"((a)[3]), "r"(b0v), "r"(b1v))

// ---------------- SMEM layout (offsets from 1024-aligned base) ----------------
// Four fp16 planes [64 k-rows][256 cols] = 512B pitch, 16B-chunk XOR swizzle.
#define SM_AH    0         // 32 KB  gal hi  (cols = r)
#define SM_AL    32768     // 32 KB  gal lo
#define SM_BH    65536     // 32 KB  prob hi (cols = s)
#define SM_BL    98304     // 32 KB  prob lo
#define SM_M2    131072    // 256*17*4 = 17408   m2[r][hc] (pitch 17)
#define SM_M1    148480    // 16*256*4 = 16384   m1[hr][s]
#define SM_TOTAL 164864
#define SM_DYN   (SM_TOTAL + 1024)

// byte offset of element (k-row, col m): chunk = m>>3 XOR (k&7)
__device__ __forceinline__ uint32_t soff(int k, int m) {
    return ((uint32_t)k << 9) + (uint32_t)(((((m >> 3)) ^ (k & 7)) << 4) + ((m & 7) << 1));
}

// hi = rn fp16, lo = rn fp16 of remainder; store 4 cols (8B each plane)
__device__ __forceinline__ void split_store_f16(char* dh, char* dl, float4 v) {
    __half2 h01 = __floats2half2_rn(v.x, v.y);
    __half2 h23 = __floats2half2_rn(v.z, v.w);
    float2 f01 = __half22float2(h01);
    float2 f23 = __half22float2(h23);
    __half2 l01 = __floats2half2_rn(v.x - f01.x, v.y - f01.y);
    __half2 l23 = __floats2half2_rn(v.z - f23.x, v.w - f23.y);
    *(uint2*)dh = make_uint2(*(uint32_t*)&h01, *(uint32_t*)&h23);
    *(uint2*)dl = make_uint2(*(uint32_t*)&l01, *(uint32_t*)&l23);
}

// ---------------- fused kernel: one CTA per (p,g), 16 warps ----------------
// C[r,s] = sum_c gal[ig][c][r] * prob[ip][c][s]
// 3-term fp16 split: C = ah*bh + ah*bl + al*bh  (al*bl ~ 2^-22, dropped)
// Warp w: m32 strip (wrow = w&7) x 128-col n-half (nhalf = w>>3).
// Last CTA to finish runs the finalize (BN -> fc -> pair-sum -> lbn -> sigmoid).
__global__ __launch_bounds__(512)
void pair_kernel(const float* __restrict__ prob, const float* __restrict__ gal,
                 const float* __restrict__ bn_gamma, const float* __restrict__ bn_beta,
                 const float* __restrict__ fc_w, const float* __restrict__ fc_b,
                 const float* __restrict__ lbn_gamma, const float* __restrict__ lbn_beta,
                 float* __restrict__ out) {
    extern __shared__ char raw[];
    const uint32_t rawaddr = smem_u32(raw);
    const uint32_t base = (rawaddr + 1023u) & ~1023u;
    char* sm = raw + (base - rawaddr);

    float* m2 = (float*)(sm + SM_M2);
    float* m1 = (float*)(sm + SM_M1);
    __shared__ double sred[24];
    __shared__ double bcast[4];
    __shared__ int sLast;

    const int blk = blockIdx.x;
    const int ip = blk / GG;
    const int ig = blk % GG;
    const int tid = threadIdx.x;
    const int wid = tid >> 5;
    const int lane = tid & 31;
    const int tq = lane & 3;
    const int qid = lane >> 2;

    // ---- stage + hi/lo split into four [k][col] swizzled planes ----
    {
        const float4* gsrc = (const float4*)(gal + (size_t)ig * CC * HWX);
        const float4* psrc = (const float4*)(prob + (size_t)ip * CC * HWX);
        #pragma unroll
        for (int i = 0; i < 8; i++) {
            const int idx = tid + i * 512;      // 4096 float4: c = idx>>6, r = (idx&63)*4
            const int c = idx >> 6;
            const int r = (idx & 63) << 2;
            const uint32_t o = soff(c, r);
            split_store_f16(sm + SM_AH + o, sm + SM_AL + o, gsrc[idx]);
            split_store_f16(sm + SM_BH + o, sm + SM_BL + o, psrc[idx]);
        }
    }
    __syncthreads();

    // ---- per-warp GEMM: m32 strip x 128-col n-half (4 chunks of 32 cols) ----
    const int wrow = wid & 7;
    const int nhalf = wid >> 3;
    const int rstrip = wrow * 32;
    const int g = lane >> 3;
    const int l7 = lane & 7;
    const uint32_t baseAH = base + SM_AH;
    const uint32_t baseAL = base + SM_AL;
    const uint32_t baseBH = base + SM_BH;
    const uint32_t baseBL = base + SM_BL;

    // A fragments, loaded once: [i][kk][4] hi and lo (m-tile i, k-step kk)
    uint32_t afh[2][4][4], afl[2][4][4];
    {
        const int kA = ((g & 2) << 2) + l7;               // + 16*kk
        #pragma unroll
        for (int i = 0; i < 2; i++) {
            const int chunkA = 4 * wrow + 2 * i + (g & 1);
            const uint32_t colA = (uint32_t)((chunkA ^ l7) << 4);
            #pragma unroll
            for (int kk = 0; kk < 4; kk++) {
                const uint32_t row = (uint32_t)((16 * kk + kA) << 9) + colA;
                LDSM4T(afh[i][kk], baseAH + row);
                LDSM4T(afl[i][kk], baseAL + row);
            }
        }
    }

    const int kB = ((g & 1) << 3) + l7;                   // + 16*kk
    const int ng = (g & 2) >> 1;                          // chunk offset for n-tiles

    #pragma unroll 1
    for (int n_c = 0; n_c < 4; n_c++) {
        const int ncg = nhalf * 4 + n_c;                  // global 32-col chunk id
        float acc[2][4][4];
        #pragma unroll
        for (int i = 0; i < 2; i++)
            #pragma unroll
            for (int j = 0; j < 4; j++)
                #pragma unroll
                for (int q = 0; q < 4; q++) acc[i][j][q] = 0.0f;

        const uint32_t c01 = (uint32_t)(((4 * ncg + 0 + ng) ^ l7) << 4);
        const uint32_t c23 = (uint32_t)(((4 * ncg + 2 + ng) ^ l7) << 4);

        #pragma unroll
        for (int kk = 0; kk < 4; kk++) {
            const uint32_t krow = (uint32_t)((16 * kk + kB) << 9);
            uint32_t bh01[4], bh23[4], bl01[4], bl23[4];
            LDSM4T(bh01, baseBH + krow + c01);
            LDSM4T(bh23, baseBH + krow + c23);
            LDSM4T(bl01, baseBL + krow + c01);
            LDSM4T(bl23, baseBL + krow + c23);

            #pragma unroll
            for (int i = 0; i < 2; i++) {
                // ah * bh
                MMA16816(acc[i][0], afh[i][kk], bh01[0], bh01[1]);
                MMA16816(acc[i][1], afh[i][kk], bh01[2], bh01[3]);
                MMA16816(acc[i][2], afh[i][kk], bh23[0], bh23[1]);
                MMA16816(acc[i][3], afh[i][kk], bh23[2], bh23[3]);
                // ah * bl
                MMA16816(acc[i][0], afh[i][kk], bl01[0], bl01[1]);
                MMA16816(acc[i][1], afh[i][kk], bl01[2], bl01[3]);
                MMA16816(acc[i][2], afh[i][kk], bl23[0], bl23[1]);
                MMA16816(acc[i][3], afh[i][kk], bl23[2], bl23[3]);
                // al * bh
                MMA16816(acc[i][0], afl[i][kk], bh01[0], bh01[1]);
                MMA16816(acc[i][1], afl[i][kk], bh01[2], bh01[3]);
                MMA16816(acc[i][2], afl[i][kk], bh23[0], bh23[1]);
                MMA16816(acc[i][3], afl[i][kk], bh23[2], bh23[3]);
            }
        }

        // ---- fold this 32x32 tile into pooled maxes ----
        // D frag: c0,c1 -> row qid, cols 2tq,2tq+1; c2,c3 -> row qid+8
        #pragma unroll
        for (int i = 0; i < 2; i++) {
            // m2: per-row max over each 16-col group (n-tiles {2gg,2gg+1})
            #pragma unroll
            for (int gg = 0; gg < 2; gg++) {
                float rm0 = fmaxf(fmaxf(acc[i][2*gg][0], acc[i][2*gg][1]),
                                  fmaxf(acc[i][2*gg+1][0], acc[i][2*gg+1][1]));
                float rm1 = fmaxf(fmaxf(acc[i][2*gg][2], acc[i][2*gg][3]),
                                  fmaxf(acc[i][2*gg+1][2], acc[i][2*gg+1][3]));
                rm0 = fmaxf(rm0, __shfl_xor_sync(0xffffffffu, rm0, 1));
                rm0 = fmaxf(rm0, __shfl_xor_sync(0xffffffffu, rm0, 2));
                rm1 = fmaxf(rm1, __shfl_xor_sync(0xffffffffu, rm1, 1));
                rm1 = fmaxf(rm1, __shfl_xor_sync(0xffffffffu, rm1, 2));
                if (tq == 0) {
                    const int hc = ncg * 2 + gg;
                    m2[(rstrip + 16 * i + qid) * 17 + hc] = rm0;
                    m2[(rstrip + 16 * i + qid + 8) * 17 + hc] = rm1;
                }
            }
            // m1: per-col max over this 16-row group (hr = 2*wrow + i)
            #pragma unroll
            for (int j = 0; j < 4; j++) {
                float cm0 = fmaxf(acc[i][j][0], acc[i][j][2]);
                float cm1 = fmaxf(acc[i][j][1], acc[i][j][3]);
                cm0 = fmaxf(cm0, __shfl_xor_sync(0xffffffffu, cm0, 4));
                cm0 = fmaxf(cm0, __shfl_xor_sync(0xffffffffu, cm0, 8));
                cm0 = fmaxf(cm0, __shfl_xor_sync(0xffffffffu, cm0, 16));
                cm1 = fmaxf(cm1, __shfl_xor_sync(0xffffffffu, cm1, 4));
                cm1 = fmaxf(cm1, __shfl_xor_sync(0xffffffffu, cm1, 8));
                cm1 = fmaxf(cm1, __shfl_xor_sync(0xffffffffu, cm1, 16));
                if (lane < 4) {
                    const int s = ncg * 32 + 8 * j + 2 * tq;
                    m1[(2 * wrow + i) * 256 + s] = cm0;
                    m1[(2 * wrow + i) * 256 + s + 1] = cm1;
                }
            }
        }
    }
    __syncthreads();

    // ---- windowed max (u = clamp(hb-2,0,12)), fc dot, global stats ----
    // Only threads 0..255 carry the 256 r/s positions.
    if (tid < 256) {
        const int hb = tid >> 4;
        const int u = min(max(hb - 2, 0), 12);

        float s2v = -3.4e38f;                          // r = tid
        #pragma unroll
        for (int t = 0; t < 4; t++) s2v = fmaxf(s2v, m2[tid * 17 + u + t]);
        float s1v = -3.4e38f;                          // s = tid
        #pragma unroll
        for (int t = 0; t < 4; t++) s1v = fmaxf(s1v, m1[(u + t) * 256 + tid]);

        const float wv = fc_w[tid];
        double dsum = (double)s1v + (double)s2v;
        double dsq  = (double)s1v * s1v + (double)s2v * s2v;
        double ddot = (double)wv * ((double)s1v + (double)s2v);

        dsum = warpRedD(dsum);
        dsq  = warpRedD(dsq);
        ddot = warpRedD(ddot);

        if (lane == 0) {
            sred[wid] = dsum;
            sred[8 + wid] = dsq;
            sred[16 + wid] = ddot;
        }
    }
    __syncthreads();
    if (tid == 0) {
        double s = 0, q = 0, d = 0;
        #pragma unroll
        for (int i = 0; i < 8; i++) { s += sred[i]; q += sred[8 + i]; d += sred[16 + i]; }
        atomicAdd(&g_sum_d, s);
        atomicAdd(&g_sumsq_d, q);
        g_dot[blk] = d;
        __threadfence();
        unsigned int old = atomicAdd(&g_count, 1u);
        sLast = (old == NPAIR - 1) ? 1 : 0;
    }
    __syncthreads();

    if (sLast) {
        // ================= fused finalize (last CTA only) =================
        // Wsum
        double wv = (tid < 256) ? (double)fc_w[tid] : 0.0;
        if (tid < 256) {
            wv = warpRedD(wv);
            if (lane == 0) sred[wid] = wv;
        }
        __syncthreads();
        if (tid == 0) {
            double s = 0;
            #pragma unroll
            for (int i = 0; i < 8; i++) s += sred[i];
            const double Wsum = s;
            // read stats through L2 (atomic read: other CTAs wrote via atomics)
            const double gs = atomicAdd(&g_sum_d, 0.0);
            const double gq = atomicAdd(&g_sumsq_d, 0.0);
            const double N1 = 2.0 * (double)NPAIR * (double)HWX;
            const double m = gs / N1;
            const double v = gq / N1 - m * m;
            const double a = (double)bn_gamma[0] * rsqrt(v + EPSV);
            bcast[0] = a;
            bcast[1] = 2.0 * (-a * m * Wsum + (double)bn_beta[0] * Wsum + (double)fc_b[0]);
            // reset for next (graph-replayed) launch
            g_sum_d = 0.0;
            g_sumsq_d = 0.0;
            g_count = 0u;
        }
        __syncthreads();
        const double a = bcast[0];
        const double cst = bcast[1];

        float pre[9];
        double ls = 0, lss = 0;
        if (tid < 256) {
            #pragma unroll
            for (int i = 0; i < 9; i++) {
                const int idx = tid + i * 256;
                float dv = __ldcg(&g_dot[idx]);     // bypass stale L1
                float pv = (float)(a * (double)dv + cst);
                pre[i] = pv;
                ls += (double)pv;
                lss += (double)pv * (double)pv;
            }
            ls = warpRedD(ls);
            lss = warpRedD(lss);
            if (lane == 0) { sred[wid] = ls; sred[8 + wid] = lss; }
        }
        __syncthreads();
        if (tid == 0) {
            double s = 0, q = 0;
            #pragma unroll
            for (int i = 0; i < 8; i++) { s += sred[i]; q += sred[8 + i]; }
            const double lm = s / (double)NPAIR;
            const double lv = q / (double)NPAIR - lm * lm;
            bcast[2] = lm;
            bcast[3] = rsqrt(lv + EPSV);
        }
        __syncthreads();
        const float lm = (float)bcast[2];
        const float linv = (float)bcast[3];
        const float lg = lbn_gamma[0];
        const float lb = lbn_beta[0];

        if (tid < 256) {
            #pragma unroll
            for (int i = 0; i < 9; i++) {
                const int idx = tid + i * 256;
                float z = lg * (pre[i] - lm) * linv + lb;
                out[idx] = 1.0f / (1.0f + expf(-z));
            }
        }
    }
}

extern "C" void kernel_launch(void* const* d_in, const int* in_sizes, int n_in,
                              void* d_out, int out_size) {
    const float* prob      = (const float*)d_in[0];
    const float* gal       = (const float*)d_in[1];
    const float* bn_gamma  = (const float*)d_in[2];
    const float* bn_beta   = (const float*)d_in[3];
    const float* fc_w      = (const float*)d_in[4];
    const float* fc_b      = (const float*)d_in[5];
    const float* lbn_gamma = (const float*)d_in[6];
    const float* lbn_beta  = (const float*)d_in[7];
    float* out = (float*)d_out;

    cudaFuncSetAttribute(pair_kernel, cudaFuncAttributeMaxDynamicSharedMemorySize, SM_DYN);

    pair_kernel<<<NPAIR, 512, SM_DYN>>>(prob, gal, bn_gamma, bn_beta,
                                        fc_w, fc_b, lbn_gamma, lbn_beta, out);
}

// round 16
// speedup vs baseline: 1.0157x; 1.0157x over previous
#include <cuda_runtime.h>
#include <cuda_fp16.h>
#include <math.h>
#include <stdint.h>

#define HWX 256
#define CC 64
#define GG 48
#define NPAIR (48*48)
#define EPSV 1e-5

// ---------------- global scratch (no allocations allowed) ----------------
// Statically zeroed; the last CTA resets them after use so every graph replay
// sees zeros again (deterministic).
__device__ double g_sum_d = 0.0;
__device__ double g_sumsq_d = 0.0;
__device__ unsigned int g_count = 0;
__device__ float  g_dot[NPAIR];

__device__ __forceinline__ double warpRedD(double v) {
    #pragma unroll
    for (int o = 16; o > 0; o >>= 1)
        v += __shfl_xor_sync(0xffffffffu, v, o);
    return v;
}

__device__ __forceinline__ uint32_t smem_u32(const void* p) {
    uint32_t a;
    asm("{ .reg .u64 t; cvta.to.shared.u64 t, %1; cvt.u32.u64 %0, t; }" : "=r"(a) : "l"(p));
    return a;
}

// ldmatrix x4 transposed (b16) — baseline PTX, works on sm_103 (non-'a')
#define LDSM4T(r, addr) \
    asm volatile("ldmatrix.sync.aligned.m8n8.x4.trans.shared.b16 {%0,%1,%2,%3}, [%4];" \
        : "=r"((r)[0]), "=r"((r)[1]), "=r"((r)[2]), "=r"((r)[3]) : "r"(addr))

// mma.sync m16n8k16 fp16 -> f32 accum — baseline PTX
#define MMA16816(d, a, b0v, b1v) \
    asm volatile("mma.sync.aligned.m16n8k16.row.col.f32.f16.f16.f32 " \
        "{%0,%1,%2,%3}, {%4,%5,%6,%7}, {%8,%9}, {%0,%1,%2,%3};" \
        : "+f"((d)[0]), "+f"((d)[1]), "+f"((d)[2]), "+f"((d)[3]) \
        : "r"((a)[0]), "r"((a)[1]), "r"((a)[2]), "r"((a)[3]), "r"(b0v), "r"(b1v))

// ---------------- SMEM layout (offsets from 1024-aligned base) ----------------
// Four fp16 planes [64 k-rows][256 cols] = 512B pitch, 16B-chunk XOR swizzle.
#define SM_AH    0         // 32 KB  gal hi  (cols = r)
#define SM_AL    32768     // 32 KB  gal lo
#define SM_BH    65536     // 32 KB  prob hi (cols = s)
#define SM_BL    98304     // 32 KB  prob lo
#define SM_M2    131072    // 256*17*4 = 17408   m2[r][hc] (pitch 17)
#define SM_M1    148480    // 16*256*4 = 16384   m1[hr][s]
#define SM_TOTAL 164864
#define SM_DYN   (SM_TOTAL + 1024)

// byte offset of element (k-row, col m): chunk = m>>3 XOR (k&7)
__device__ __forceinline__ uint32_t soff(int k, int m) {
    return ((uint32_t)k << 9) + (uint32_t)(((((m >> 3)) ^ (k & 7)) << 4) + ((m & 7) << 1));
}

// hi = rn fp16, lo = rn fp16 of remainder; store 4 cols (8B each plane)
__device__ __forceinline__ void split_store_f16(char* dh, char* dl, float4 v) {
    __half2 h01 = __floats2half2_rn(v.x, v.y);
    __half2 h23 = __floats2half2_rn(v.z, v.w);
    float2 f01 = __half22float2(h01);
    float2 f23 = __half22float2(h23);
    __half2 l01 = __floats2half2_rn(v.x - f01.x, v.y - f01.y);
    __half2 l23 = __floats2half2_rn(v.z - f23.x, v.w - f23.y);
    *(uint2*)dh = make_uint2(*(uint32_t*)&h01, *(uint32_t*)&h23);
    *(uint2*)dl = make_uint2(*(uint32_t*)&l01, *(uint32_t*)&l23);
}

// ---------------- fused kernel: one CTA per (p,g), 16 warps ----------------
// C[r,s] = sum_c gal[ig][c][r] * prob[ip][c][s]
// 3-term fp16 split: C = ah*bh + ah*bl + al*bh  (al*bl ~ 2^-22, dropped)
// Warp w: m32 strip (wrow = w&7) x 128-col n-half (nhalf = w>>3).
// MMAs issued TERM-MAJOR per kk: 8 independent MMAs between same-acc writes.
// Last CTA to finish runs the finalize (BN -> fc -> pair-sum -> lbn -> sigmoid).
__global__ __launch_bounds__(512)
void pair_kernel(const float* __restrict__ prob, const float* __restrict__ gal,
                 const float* __restrict__ bn_gamma, const float* __restrict__ bn_beta,
                 const float* __restrict__ fc_w, const float* __restrict__ fc_b,
                 const float* __restrict__ lbn_gamma, const float* __restrict__ lbn_beta,
                 float* __restrict__ out) {
    extern __shared__ char raw[];
    const uint32_t rawaddr = smem_u32(raw);
    const uint32_t base = (rawaddr + 1023u) & ~1023u;
    char* sm = raw + (base - rawaddr);

    float* m2 = (float*)(sm + SM_M2);
    float* m1 = (float*)(sm + SM_M1);
    __shared__ double sred[24];
    __shared__ double bcast[4];
    __shared__ int sLast;

    const int blk = blockIdx.x;
    const int ip = blk / GG;
    const int ig = blk % GG;
    const int tid = threadIdx.x;
    const int wid = tid >> 5;
    const int lane = tid & 31;
    const int tq = lane & 3;
    const int qid = lane >> 2;

    // ---- stage + hi/lo split into four [k][col] swizzled planes ----
    {
        const float4* gsrc = (const float4*)(gal + (size_t)ig * CC * HWX);
        const float4* psrc = (const float4*)(prob + (size_t)ip * CC * HWX);
        #pragma unroll
        for (int i = 0; i < 8; i++) {
            const int idx = tid + i * 512;      // 4096 float4: c = idx>>6, r = (idx&63)*4
            const int c = idx >> 6;
            const int r = (idx & 63) << 2;
            const uint32_t o = soff(c, r);
            split_store_f16(sm + SM_AH + o, sm + SM_AL + o, gsrc[idx]);
            split_store_f16(sm + SM_BH + o, sm + SM_BL + o, psrc[idx]);
        }
    }
    __syncthreads();

    // ---- per-warp GEMM: m32 strip x 128-col n-half (4 chunks of 32 cols) ----
    const int wrow = wid & 7;
    const int nhalf = wid >> 3;
    const int rstrip = wrow * 32;
    const int g = lane >> 3;
    const int l7 = lane & 7;
    const uint32_t baseAH = base + SM_AH;
    const uint32_t baseAL = base + SM_AL;
    const uint32_t baseBH = base + SM_BH;
    const uint32_t baseBL = base + SM_BL;

    // A fragments, loaded once: [i][kk][4] hi and lo (m-tile i, k-step kk)
    uint32_t afh[2][4][4], afl[2][4][4];
    {
        const int kA = ((g & 2) << 2) + l7;               // + 16*kk
        #pragma unroll
        for (int i = 0; i < 2; i++) {
            const int chunkA = 4 * wrow + 2 * i + (g & 1);
            const uint32_t colA = (uint32_t)((chunkA ^ l7) << 4);
            #pragma unroll
            for (int kk = 0; kk < 4; kk++) {
                const uint32_t row = (uint32_t)((16 * kk + kA) << 9) + colA;
                LDSM4T(afh[i][kk], baseAH + row);
                LDSM4T(afl[i][kk], baseAL + row);
            }
        }
    }

    const int kB = ((g & 1) << 3) + l7;                   // + 16*kk
    const int ng = (g & 2) >> 1;                          // chunk offset for n-tiles

    #pragma unroll 2
    for (int n_c = 0; n_c < 4; n_c++) {
        const int ncg = nhalf * 4 + n_c;                  // global 32-col chunk id
        float acc[2][4][4];
        #pragma unroll
        for (int i = 0; i < 2; i++)
            #pragma unroll
            for (int j = 0; j < 4; j++)
                #pragma unroll
                for (int q = 0; q < 4; q++) acc[i][j][q] = 0.0f;

        const uint32_t c01 = (uint32_t)(((4 * ncg + 0 + ng) ^ l7) << 4);
        const uint32_t c23 = (uint32_t)(((4 * ncg + 2 + ng) ^ l7) << 4);

        #pragma unroll
        for (int kk = 0; kk < 4; kk++) {
            const uint32_t krow = (uint32_t)((16 * kk + kB) << 9);
            uint32_t bh01[4], bh23[4], bl01[4], bl23[4];
            LDSM4T(bh01, baseBH + krow + c01);
            LDSM4T(bh23, baseBH + krow + c23);
            LDSM4T(bl01, baseBL + krow + c01);
            LDSM4T(bl23, baseBL + krow + c23);

            // TERM-MAJOR: 8 independent MMAs per pass; same-acc writes 8 apart.
            // pass 1: ah * bh
            MMA16816(acc[0][0], afh[0][kk], bh01[0], bh01[1]);
            MMA16816(acc[0][1], afh[0][kk], bh01[2], bh01[3]);
            MMA16816(acc[0][2], afh[0][kk], bh23[0], bh23[1]);
            MMA16816(acc[0][3], afh[0][kk], bh23[2], bh23[3]);
            MMA16816(acc[1][0], afh[1][kk], bh01[0], bh01[1]);
            MMA16816(acc[1][1], afh[1][kk], bh01[2], bh01[3]);
            MMA16816(acc[1][2], afh[1][kk], bh23[0], bh23[1]);
            MMA16816(acc[1][3], afh[1][kk], bh23[2], bh23[3]);
            // pass 2: ah * bl
            MMA16816(acc[0][0], afh[0][kk], bl01[0], bl01[1]);
            MMA16816(acc[0][1], afh[0][kk], bl01[2], bl01[3]);
            MMA16816(acc[0][2], afh[0][kk], bl23[0], bl23[1]);
            MMA16816(acc[0][3], afh[0][kk], bl23[2], bl23[3]);
            MMA16816(acc[1][0], afh[1][kk], bl01[0], bl01[1]);
            MMA16816(acc[1][1], afh[1][kk], bl01[2], bl01[3]);
            MMA16816(acc[1][2], afh[1][kk], bl23[0], bl23[1]);
            MMA16816(acc[1][3], afh[1][kk], bl23[2], bl23[3]);
            // pass 3: al * bh
            MMA16816(acc[0][0], afl[0][kk], bh01[0], bh01[1]);
            MMA16816(acc[0][1], afl[0][kk], bh01[2], bh01[3]);
            MMA16816(acc[0][2], afl[0][kk], bh23[0], bh23[1]);
            MMA16816(acc[0][3], afl[0][kk], bh23[2], bh23[3]);
            MMA16816(acc[1][0], afl[1][kk], bh01[0], bh01[1]);
            MMA16816(acc[1][1], afl[1][kk], bh01[2], bh01[3]);
            MMA16816(acc[1][2], afl[1][kk], bh23[0], bh23[1]);
            MMA16816(acc[1][3], afl[1][kk], bh23[2], bh23[3]);
        }

        // ---- fold this 32x32 tile into pooled maxes ----
        // D frag: c0,c1 -> row qid, cols 2tq,2tq+1; c2,c3 -> row qid+8
        #pragma unroll
        for (int i = 0; i < 2; i++) {
            // m2: per-row max over each 16-col group (n-tiles {2gg,2gg+1})
            #pragma unroll
            for (int gg = 0; gg < 2; gg++) {
                float rm0 = fmaxf(fmaxf(acc[i][2*gg][0], acc[i][2*gg][1]),
                                  fmaxf(acc[i][2*gg+1][0], acc[i][2*gg+1][1]));
                float rm1 = fmaxf(fmaxf(acc[i][2*gg][2], acc[i][2*gg][3]),
                                  fmaxf(acc[i][2*gg+1][2], acc[i][2*gg+1][3]));
                rm0 = fmaxf(rm0, __shfl_xor_sync(0xffffffffu, rm0, 1));
                rm0 = fmaxf(rm0, __shfl_xor_sync(0xffffffffu, rm0, 2));
                rm1 = fmaxf(rm1, __shfl_xor_sync(0xffffffffu, rm1, 1));
                rm1 = fmaxf(rm1, __shfl_xor_sync(0xffffffffu, rm1, 2));
                if (tq == 0) {
                    const int hc = ncg * 2 + gg;
                    m2[(rstrip + 16 * i + qid) * 17 + hc] = rm0;
                    m2[(rstrip + 16 * i + qid + 8) * 17 + hc] = rm1;
                }
            }
            // m1: per-col max over this 16-row group (hr = 2*wrow + i)
            #pragma unroll
            for (int j = 0; j < 4; j++) {
                float cm0 = fmaxf(acc[i][j][0], acc[i][j][2]);
                float cm1 = fmaxf(acc[i][j][1], acc[i][j][3]);
                cm0 = fmaxf(cm0, __shfl_xor_sync(0xffffffffu, cm0, 4));
                cm0 = fmaxf(cm0, __shfl_xor_sync(0xffffffffu, cm0, 8));
                cm0 = fmaxf(cm0, __shfl_xor_sync(0xffffffffu, cm0, 16));
                cm1 = fmaxf(cm1, __shfl_xor_sync(0xffffffffu, cm1, 4));
                cm1 = fmaxf(cm1, __shfl_xor_sync(0xffffffffu, cm1, 8));
                cm1 = fmaxf(cm1, __shfl_xor_sync(0xffffffffu, cm1, 16));
                if (lane < 4) {
                    const int s = ncg * 32 + 8 * j + 2 * tq;
                    m1[(2 * wrow + i) * 256 + s] = cm0;
                    m1[(2 * wrow + i) * 256 + s + 1] = cm1;
                }
            }
        }
    }
    __syncthreads();

    // ---- windowed max (u = clamp(hb-2,0,12)), fc dot, global stats ----
    // Only threads 0..255 carry the 256 r/s positions.
    if (tid < 256) {
        const int hb = tid >> 4;
        const int u = min(max(hb - 2, 0), 12);

        float s2v = -3.4e38f;                          // r = tid
        #pragma unroll
        for (int t = 0; t < 4; t++) s2v = fmaxf(s2v, m2[tid * 17 + u + t]);
        float s1v = -3.4e38f;                          // s = tid
        #pragma unroll
        for (int t = 0; t < 4; t++) s1v = fmaxf(s1v, m1[(u + t) * 256 + tid]);

        const float wv = fc_w[tid];
        double dsum = (double)s1v + (double)s2v;
        double dsq  = (double)s1v * s1v + (double)s2v * s2v;
        double ddot = (double)wv * ((double)s1v + (double)s2v);

        dsum = warpRedD(dsum);
        dsq  = warpRedD(dsq);
        ddot = warpRedD(ddot);

        if (lane == 0) {
            sred[wid] = dsum;
            sred[8 + wid] = dsq;
            sred[16 + wid] = ddot;
        }
    }
    __syncthreads();
    if (tid == 0) {
        double s = 0, q = 0, d = 0;
        #pragma unroll
        for (int i = 0; i < 8; i++) { s += sred[i]; q += sred[8 + i]; d += sred[16 + i]; }
        atomicAdd(&g_sum_d, s);
        atomicAdd(&g_sumsq_d, q);
        g_dot[blk] = d;
        __threadfence();
        unsigned int old = atomicAdd(&g_count, 1u);
        sLast = (old == NPAIR - 1) ? 1 : 0;
    }
    __syncthreads();

    if (sLast) {
        // ================= fused finalize (last CTA only) =================
        // Wsum
        double wv = (tid < 256) ? (double)fc_w[tid] : 0.0;
        if (tid < 256) {
            wv = warpRedD(wv);
            if (lane == 0) sred[wid] = wv;
        }
        __syncthreads();
        if (tid == 0) {
            double s = 0;
            #pragma unroll
            for (int i = 0; i < 8; i++) s += sred[i];
            const double Wsum = s;
            // read stats through L2 (atomic read: other CTAs wrote via atomics)
            const double gs = atomicAdd(&g_sum_d, 0.0);
            const double gq = atomicAdd(&g_sumsq_d, 0.0);
            const double N1 = 2.0 * (double)NPAIR * (double)HWX;
            const double m = gs / N1;
            const double v = gq / N1 - m * m;
            const double a = (double)bn_gamma[0] * rsqrt(v + EPSV);
            bcast[0] = a;
            bcast[1] = 2.0 * (-a * m * Wsum + (double)bn_beta[0] * Wsum + (double)fc_b[0]);
            // reset for next (graph-replayed) launch
            g_sum_d = 0.0;
            g_sumsq_d = 0.0;
            g_count = 0u;
        }
        __syncthreads();
        const double a = bcast[0];
        const double cst = bcast[1];

        float pre[9];
        double ls = 0, lss = 0;
        if (tid < 256) {
            #pragma unroll
            for (int i = 0; i < 9; i++) {
                const int idx = tid + i * 256;
                float dv = __ldcg(&g_dot[idx]);     // bypass stale L1
                float pv = (float)(a * (double)dv + cst);
                pre[i] = pv;
                ls += (double)pv;
                lss += (double)pv * (double)pv;
            }
            ls = warpRedD(ls);
            lss = warpRedD(lss);
            if (lane == 0) { sred[wid] = ls; sred[8 + wid] = lss; }
        }
        __syncthreads();
        if (tid == 0) {
            double s = 0, q = 0;
            #pragma unroll
            for (int i = 0; i < 8; i++) { s += sred[i]; q += sred[8 + i]; }
            const double lm = s / (double)NPAIR;
            const double lv = q / (double)NPAIR - lm * lm;
            bcast[2] = lm;
            bcast[3] = rsqrt(lv + EPSV);
        }
        __syncthreads();
        const float lm = (float)bcast[2];
        const float linv = (float)bcast[3];
        const float lg = lbn_gamma[0];
        const float lb = lbn_beta[0];

        if (tid < 256) {
            #pragma unroll
            for (int i = 0; i < 9; i++) {
                const int idx = tid + i * 256;
                float z = lg * (pre[i] - lm) * linv + lb;
                out[idx] = 1.0f / (1.0f + expf(-z));
            }
        }
    }
}

extern "C" void kernel_launch(void* const* d_in, const int* in_sizes, int n_in,
                              void* d_out, int out_size) {
    const float* prob      = (const float*)d_in[0];
    const float* gal       = (const float*)d_in[1];
    const float* bn_gamma  = (const float*)d_in[2];
    const float* bn_beta   = (const float*)d_in[3];
    const float* fc_w      = (const float*)d_in[4];
    const float* fc_b      = (const float*)d_in[5];
    const float* lbn_gamma = (const float*)d_in[6];
    const float* lbn_beta  = (const float*)d_in[7];
    float* out = (float*)d_out;

    cudaFuncSetAttribute(pair_kernel, cudaFuncAttributeMaxDynamicSharedMemorySize, SM_DYN);

    pair_kernel<<<NPAIR, 512, SM_DYN>>>(prob, gal, bn_gamma, bn_beta,
                                        fc_w, fc_b, lbn_gamma, lbn_beta, out);
}

// round 17
// speedup vs baseline: 1.0943x; 1.0774x over previous
#include <cuda_runtime.h>
#include <cuda_fp16.h>
#include <math.h>
#include <stdint.h>

#define HWX 256
#define CC 64
#define GG 48
#define NPAIR (48*48)
#define EPSV 1e-5

// ---------------- global scratch (no allocations allowed) ----------------
__device__ double g_sum_d = 0.0;
__device__ double g_sumsq_d = 0.0;
__device__ unsigned int g_count = 0;
__device__ float  g_dot[NPAIR];

__device__ __forceinline__ double warpRedD(double v) {
    #pragma unroll
    for (int o = 16; o > 0; o >>= 1)
        v += __shfl_xor_sync(0xffffffffu, v, o);
    return v;
}

__device__ __forceinline__ uint32_t smem_u32(const void* p) {
    uint32_t a;
    asm("{ .reg .u64 t; cvta.to.shared.u64 t, %1; cvt.u32.u64 %0, t; }" : "=r"(a) : "l"(p));
    return a;
}

// ldmatrix x4 transposed (b16) — baseline PTX, works on sm_103 (non-'a')
#define LDSM4T(r, addr) \
    asm volatile("ldmatrix.sync.aligned.m8n8.x4.trans.shared.b16 {%0,%1,%2,%3}, [%4];" \
        : "=r"((r)[0]), "=r"((r)[1]), "=r"((r)[2]), "=r"((r)[3]) : "r"(addr))

// mma.sync m16n8k16 fp16 -> f32 accum — baseline PTX
#define MMA16816(d, a, b0v, b1v) \
    asm volatile("mma.sync.aligned.m16n8k16.row.col.f32.f16.f16.f32 " \
        "{%0,%1,%2,%3}, {%4,%5,%6,%7}, {%8,%9}, {%0,%1,%2,%3};" \
        : "+f"((d)[0]), "+f"((d)[1]), "+f"((d)[2]), "+f"((d)[3]) \
        : "r"((a)[0]), "r"((a)[1]), "r"((a)[2]), "r"((a)[3]), "r"(b0v), "r"(b1v))

// ---------------- SMEM layout (offsets from 1024-aligned base) ----------------
// Four fp16 planes [64 k-rows][256 cols] = 512B pitch, 16B-chunk XOR swizzle.
#define SM_AH    0         // 32 KB  gal hi  (cols = r)
#define SM_AL    32768     // 32 KB  gal lo
#define SM_BH    65536     // 32 KB  prob hi (cols = s)
#define SM_BL    98304     // 32 KB  prob lo
#define SM_M2    131072    // 256*17*4 = 17408   m2[r][hc] (pitch 17)
#define SM_M1    148480    // 16*256*4 = 16384   m1[hr][s]
#define SM_TOTAL 164864
#define SM_DYN   (SM_TOTAL + 1024)

// byte offset of element (k-row, col m): chunk = m>>3 XOR (k&7)
__device__ __forceinline__ uint32_t soff(int k, int m) {
    return ((uint32_t)k << 9) + (uint32_t)(((((m >> 3)) ^ (k & 7)) << 4) + ((m & 7) << 1));
}

// hi = rn fp16, lo = rn fp16 of remainder; store 4 cols (8B each plane)
__device__ __forceinline__ void split_store_f16(char* dh, char* dl, float4 v) {
    __half2 h01 = __floats2half2_rn(v.x, v.y);
    __half2 h23 = __floats2half2_rn(v.z, v.w);
    float2 f01 = __half22float2(h01);
    float2 f23 = __half22float2(h23);
    __half2 l01 = __floats2half2_rn(v.x - f01.x, v.y - f01.y);
    __half2 l23 = __floats2half2_rn(v.z - f23.x, v.w - f23.y);
    *(uint2*)dh = make_uint2(*(uint32_t*)&h01, *(uint32_t*)&h23);
    *(uint2*)dl = make_uint2(*(uint32_t*)&l01, *(uint32_t*)&l23);
}

// ---------------- fused kernel: one CTA per (p,g), 16 warps ----------------
// C[r,s] = sum_c gal[ig][c][r] * prob[ip][c][s]
// 3-term fp16 split: C = ah*bh + ah*bl + al*bh  (al*bl ~ 2^-22, dropped)
// Warp w: m16 strip (rows 16w..16w+15) x all 256 cols, 8 chunks of 32.
// Flattened (chunk,kk) pipeline: next step's B LDSMs issued before this
// step's MMAs (double-buffered B fragments).
// Last CTA to finish runs the finalize (BN -> fc -> pair-sum -> lbn -> sigmoid).
__global__ __launch_bounds__(512)
void pair_kernel(const float* __restrict__ prob, const float* __restrict__ gal,
                 const float* __restrict__ bn_gamma, const float* __restrict__ bn_beta,
                 const float* __restrict__ fc_w, const float* __restrict__ fc_b,
                 const float* __restrict__ lbn_gamma, const float* __restrict__ lbn_beta,
                 float* __restrict__ out) {
    extern __shared__ char raw[];
    const uint32_t rawaddr = smem_u32(raw);
    const uint32_t base = (rawaddr + 1023u) & ~1023u;
    char* sm = raw + (base - rawaddr);

    float* m2 = (float*)(sm + SM_M2);
    float* m1 = (float*)(sm + SM_M1);
    __shared__ double sred[24];
    __shared__ double bcast[4];
    __shared__ int sLast;

    const int blk = blockIdx.x;
    const int ip = blk / GG;
    const int ig = blk % GG;
    const int tid = threadIdx.x;
    const int wid = tid >> 5;
    const int lane = tid & 31;
    const int tq = lane & 3;
    const int qid = lane >> 2;

    // ---- stage + hi/lo split into four [k][col] swizzled planes ----
    {
        const float4* gsrc = (const float4*)(gal + (size_t)ig * CC * HWX);
        const float4* psrc = (const float4*)(prob + (size_t)ip * CC * HWX);
        #pragma unroll
        for (int i = 0; i < 8; i++) {
            const int idx = tid + i * 512;      // 4096 float4: c = idx>>6, r = (idx&63)*4
            const int c = idx >> 6;
            const int r = (idx & 63) << 2;
            const uint32_t o = soff(c, r);
            split_store_f16(sm + SM_AH + o, sm + SM_AL + o, gsrc[idx]);
            split_store_f16(sm + SM_BH + o, sm + SM_BL + o, psrc[idx]);
        }
    }
    __syncthreads();

    // ---- per-warp GEMM: m16 strip x 256 cols, pipelined over 32 steps ----
    const int g = lane >> 3;
    const int l7 = lane & 7;
    const uint32_t baseAH = base + SM_AH;
    const uint32_t baseAL = base + SM_AL;
    const uint32_t baseBH = base + SM_BH;
    const uint32_t baseBL = base + SM_BL;

    // A fragments, loaded once: [kk][4] hi and lo
    uint32_t afh[4][4], afl[4][4];
    {
        const int kA = ((g & 2) << 2) + l7;               // + 16*kk
        const int chunkA = 2 * wid + (g & 1);
        const uint32_t colA = (uint32_t)((chunkA ^ l7) << 4);
        #pragma unroll
        for (int kk = 0; kk < 4; kk++) {
            const uint32_t row = (uint32_t)((16 * kk + kA) << 9) + colA;
            LDSM4T(afh[kk], baseAH + row);
            LDSM4T(afl[kk], baseAL + row);
        }
    }

    const int kB = ((g & 1) << 3) + l7;                   // + 16*kk
    const int ng = (g & 2) >> 1;                          // chunk offset for n-tiles

    // B fragment double buffer: [buf][0..7]=bh01,bh23  [8..15]=bl01,bl23
    uint32_t bq[2][16];

    // load B frags for flattened step (n_c = step>>2, kk = step&3)
    #define LOAD_B(step, bf) do { \
        const int ncg_ = (step) >> 2; \
        const int kk_ = (step) & 3; \
        const uint32_t krow_ = (uint32_t)((16 * kk_ + kB) << 9); \
        const uint32_t c01_ = (uint32_t)(((4 * ncg_ + 0 + ng) ^ l7) << 4); \
        const uint32_t c23_ = (uint32_t)(((4 * ncg_ + 2 + ng) ^ l7) << 4); \
        LDSM4T(&(bf)[0],  baseBH + krow_ + c01_); \
        LDSM4T(&(bf)[4],  baseBH + krow_ + c23_); \
        LDSM4T(&(bf)[8],  baseBL + krow_ + c01_); \
        LDSM4T(&(bf)[12], baseBL + krow_ + c23_); \
    } while (0)

    float acc[4][4];
    #pragma unroll
    for (int j = 0; j < 4; j++)
        #pragma unroll
        for (int q = 0; q < 4; q++) acc[j][q] = 0.0f;

    LOAD_B(0, bq[0]);

    #pragma unroll
    for (int step = 0; step < 32; step++) {
        uint32_t* cur = bq[step & 1];
        if (step < 31) LOAD_B(step + 1, bq[(step + 1) & 1]);

        const int kk = step & 3;
        // term-major: 4 independent accs per term pass
        // ah * bh
        MMA16816(acc[0], afh[kk], cur[0],  cur[1]);
        MMA16816(acc[1], afh[kk], cur[2],  cur[3]);
        MMA16816(acc[2], afh[kk], cur[4],  cur[5]);
        MMA16816(acc[3], afh[kk], cur[6],  cur[7]);
        // ah * bl
        MMA16816(acc[0], afh[kk], cur[8],  cur[9]);
        MMA16816(acc[1], afh[kk], cur[10], cur[11]);
        MMA16816(acc[2], afh[kk], cur[12], cur[13]);
        MMA16816(acc[3], afh[kk], cur[14], cur[15]);
        // al * bh
        MMA16816(acc[0], afl[kk], cur[0],  cur[1]);
        MMA16816(acc[1], afl[kk], cur[2],  cur[3]);
        MMA16816(acc[2], afl[kk], cur[4],  cur[5]);
        MMA16816(acc[3], afl[kk], cur[6],  cur[7]);

        if (kk == 3) {
            const int ncg = step >> 2;
            // ---- fold this 16x32 tile into pooled maxes (merge-tree) ----
            // D frag: c0,c1 -> row qid, cols 2tq,2tq+1; c2,c3 -> row qid+8

            // m2: per-row max over each 16-col group (n-tiles {2gg,2gg+1})
            {
                float rm0[2], rm1[2];
                #pragma unroll
                for (int gg = 0; gg < 2; gg++) {
                    rm0[gg] = fmaxf(fmaxf(acc[2*gg][0], acc[2*gg][1]),
                                    fmaxf(acc[2*gg+1][0], acc[2*gg+1][1]));
                    rm1[gg] = fmaxf(fmaxf(acc[2*gg][2], acc[2*gg][3]),
                                    fmaxf(acc[2*gg+1][2], acc[2*gg+1][3]));
                    rm0[gg] = fmaxf(rm0[gg], __shfl_xor_sync(0xffffffffu, rm0[gg], 1));
                    rm1[gg] = fmaxf(rm1[gg], __shfl_xor_sync(0xffffffffu, rm1[gg], 1));
                }
                // merge row-half by lane bit0 (both values reduced over tq bit0)
                float mv[2];
                #pragma unroll
                for (int gg = 0; gg < 2; gg++) {
                    mv[gg] = (lane & 1) ? rm1[gg] : rm0[gg];
                    mv[gg] = fmaxf(mv[gg], __shfl_xor_sync(0xffffffffu, mv[gg], 2));
                }
                if (!(lane & 2)) {
                    const int row = wid * 16 + qid + 8 * (lane & 1);
                    m2[row * 17 + ncg * 2 + 0] = mv[0];
                    m2[row * 17 + ncg * 2 + 1] = mv[1];
                }
            }

            // m1: per-col max over this warp's 16-row group (hr = wid)
            {
                float cm[4][2];
                #pragma unroll
                for (int j = 0; j < 4; j++) {
                    cm[j][0] = fmaxf(acc[j][0], acc[j][2]);
                    cm[j][1] = fmaxf(acc[j][1], acc[j][3]);
                    cm[j][0] = fmaxf(cm[j][0], __shfl_xor_sync(0xffffffffu, cm[j][0], 4));
                    cm[j][1] = fmaxf(cm[j][1], __shfl_xor_sync(0xffffffffu, cm[j][1], 4));
                }
                // merge col-parity by lane bit2 (reduced over qid bit0)
                float u[4];
                #pragma unroll
                for (int j = 0; j < 4; j++) {
                    u[j] = (lane & 4) ? cm[j][1] : cm[j][0];
                    u[j] = fmaxf(u[j], __shfl_xor_sync(0xffffffffu, u[j], 8));
                }
                // merge j-parity by lane bit3 (reduced over qid bits 0,1)
                float w[2];
                #pragma unroll
                for (int t = 0; t < 2; t++) {
                    w[t] = (lane & 8) ? u[2*t + 1] : u[2*t];
                    w[t] = fmaxf(w[t], __shfl_xor_sync(0xffffffffu, w[t], 16));
                }
                if (lane < 16) {
                    const int c  = (lane >> 2) & 1;
                    const int jb = (lane >> 3) & 1;
                    #pragma unroll
                    for (int t = 0; t < 2; t++) {
                        const int s = ncg * 32 + 8 * (2*t + jb) + 2 * tq + c;
                        m1[wid * 256 + s] = w[t];
                    }
                }
            }

            // reset accumulators for next chunk
            #pragma unroll
            for (int j = 0; j < 4; j++)
                #pragma unroll
                for (int q = 0; q < 4; q++) acc[j][q] = 0.0f;
        }
    }
    #undef LOAD_B
    __syncthreads();

    // ---- windowed max (u = clamp(hb-2,0,12)), fc dot, global stats ----
    // Only threads 0..255 carry the 256 r/s positions.
    if (tid < 256) {
        const int hb = tid >> 4;
        const int u = min(max(hb - 2, 0), 12);

        float s2v = -3.4e38f;                          // r = tid
        #pragma unroll
        for (int t = 0; t < 4; t++) s2v = fmaxf(s2v, m2[tid * 17 + u + t]);
        float s1v = -3.4e38f;                          // s = tid
        #pragma unroll
        for (int t = 0; t < 4; t++) s1v = fmaxf(s1v, m1[(u + t) * 256 + tid]);

        const float wv = fc_w[tid];
        double dsum = (double)s1v + (double)s2v;
        double dsq  = (double)s1v * s1v + (double)s2v * s2v;
        double ddot = (double)wv * ((double)s1v + (double)s2v);

        dsum = warpRedD(dsum);
        dsq  = warpRedD(dsq);
        ddot = warpRedD(ddot);

        if (lane == 0) {
            sred[wid] = dsum;
            sred[8 + wid] = dsq;
            sred[16 + wid] = ddot;
        }
    }
    __syncthreads();
    if (tid == 0) {
        double s = 0, q = 0, d = 0;
        #pragma unroll
        for (int i = 0; i < 8; i++) { s += sred[i]; q += sred[8 + i]; d += sred[16 + i]; }
        atomicAdd(&g_sum_d, s);
        atomicAdd(&g_sumsq_d, q);
        g_dot[blk] = d;
        __threadfence();
        unsigned int old = atomicAdd(&g_count, 1u);
        sLast = (old == NPAIR - 1) ? 1 : 0;
    }
    __syncthreads();

    if (sLast) {
        // ================= fused finalize (last CTA only) =================
        // Wsum
        double wv = (tid < 256) ? (double)fc_w[tid] : 0.0;
        if (tid < 256) {
            wv = warpRedD(wv);
            if (lane == 0) sred[wid] = wv;
        }
        __syncthreads();
        if (tid == 0) {
            double s = 0;
            #pragma unroll
            for (int i = 0; i < 8; i++) s += sred[i];
            const double Wsum = s;
            // read stats through L2 (atomic read: other CTAs wrote via atomics)
            const double gs = atomicAdd(&g_sum_d, 0.0);
            const double gq = atomicAdd(&g_sumsq_d, 0.0);
            const double N1 = 2.0 * (double)NPAIR * (double)HWX;
            const double m = gs / N1;
            const double v = gq / N1 - m * m;
            const double a = (double)bn_gamma[0] * rsqrt(v + EPSV);
            bcast[0] = a;
            bcast[1] = 2.0 * (-a * m * Wsum + (double)bn_beta[0] * Wsum + (double)fc_b[0]);
            // reset for next (graph-replayed) launch
            g_sum_d = 0.0;
            g_sumsq_d = 0.0;
            g_count = 0u;
        }
        __syncthreads();
        const double a = bcast[0];
        const double cst = bcast[1];

        float pre[9];
        double ls = 0, lss = 0;
        if (tid < 256) {
            #pragma unroll
            for (int i = 0; i < 9; i++) {
                const int idx = tid + i * 256;
                float dv = __ldcg(&g_dot[idx]);     // bypass stale L1
                float pv = (float)(a * (double)dv + cst);
                pre[i] = pv;
                ls += (double)pv;
                lss += (double)pv * (double)pv;
            }
            ls = warpRedD(ls);
            lss = warpRedD(lss);
            if (lane == 0) { sred[wid] = ls; sred[8 + wid] = lss; }
        }
        __syncthreads();
        if (tid == 0) {
            double s = 0, q = 0;
            #pragma unroll
            for (int i = 0; i < 8; i++) { s += sred[i]; q += sred[8 + i]; }
            const double lm = s / (double)NPAIR;
            const double lv = q / (double)NPAIR - lm * lm;
            bcast[2] = lm;
            bcast[3] = rsqrt(lv + EPSV);
        }
        __syncthreads();
        const float lm = (float)bcast[2];
        const float linv = (float)bcast[3];
        const float lg = lbn_gamma[0];
        const float lb = lbn_beta[0];

        if (tid < 256) {
            #pragma unroll
            for (int i = 0; i < 9; i++) {
                const int idx = tid + i * 256;
                float z = lg * (pre[i] - lm) * linv + lb;
                out[idx] = 1.0f / (1.0f + expf(-z));
            }
        }
    }
}

extern "C" void kernel_launch(void* const* d_in, const int* in_sizes, int n_in,
                              void* d_out, int out_size) {
    const float* prob      = (const float*)d_in[0];
    const float* gal       = (const float*)d_in[1];
    const float* bn_gamma  = (const float*)d_in[2];
    const float* bn_beta   = (const float*)d_in[3];
    const float* fc_w      = (const float*)d_in[4];
    const float* fc_b      = (const float*)d_in[5];
    const float* lbn_gamma = (const float*)d_in[6];
    const float* lbn_beta  = (const float*)d_in[7];
    float* out = (float*)d_out;

    cudaFuncSetAttribute(pair_kernel, cudaFuncAttributeMaxDynamicSharedMemorySize, SM_DYN);

    pair_kernel<<<NPAIR, 512, SM_DYN>>>(prob, gal, bn_gamma, bn_beta,
                                        fc_w, fc_b, lbn_gamma, lbn_beta, out);
}